// round 5
// baseline (speedup 1.0000x reference)
#include <cuda_runtime.h>
#include <cuda_bf16.h>
#include <math.h>
#include <stdint.h>

// ---------------------------------------------------------------------------
// PrefilledAttention: x[8,2048,1024] f32; Wq,Wk[128,1024]; Wv[1024,1024]
//   q = x Wq^T; k = x Wk^T; v = x Wv^T
//   s = (q k^T)/sqrt(128); p = softmax(s); out = p v
// Round-5: bf16x3 split-precision tensor-core GEMM (mma.sync m16n8k16),
//          single TRANSB-style path (v pre-transposed), fp32-class accuracy.
// ---------------------------------------------------------------------------

#define B_   8
#define S_   2048
#define D_   1024
#define R_   128
#define BS_  (B_ * S_)           // 16384

__device__ float g_q [(size_t)BS_ * R_];           //   8 MB
__device__ float g_k [(size_t)BS_ * R_];           //   8 MB
__device__ float g_v [(size_t)BS_ * D_];           //  64 MB
__device__ float g_vt[(size_t)BS_ * D_];           //  64 MB (per-batch [D][S])
__device__ float g_s [(size_t)B_ * S_ * S_];       // 128 MB

// ---------------------------------------------------------------------------
// bf16x3 tensor-core GEMM:
//   C[m,n] = alpha * sum_k A[m,k] * B[n,k]
// A: [M,K] row-major (k contiguous), B: [N,K] row-major (k contiguous).
// Block tile 128x128x32, 256 threads (8 warps as 2x4), warp tile 64x32,
// mma.sync.m16n8k16 bf16, fp32 accum, 3-term split per product.
// All dims are multiples of tile sizes (M%128==0, N%128==0, K%32==0).
// ---------------------------------------------------------------------------
#define SM_STRIDE 40   // bf16 elements per smem row (conflict-free for frags)

__device__ __forceinline__ void mma_bf16(float c[4],
                                         uint32_t a0, uint32_t a1,
                                         uint32_t a2, uint32_t a3,
                                         uint32_t b0, uint32_t b1)
{
    asm volatile(
        "mma.sync.aligned.m16n8k16.row.col.f32.bf16.bf16.f32 "
        "{%0,%1,%2,%3}, {%4,%5,%6,%7}, {%8,%9}, {%0,%1,%2,%3};\n"
        : "+f"(c[0]), "+f"(c[1]), "+f"(c[2]), "+f"(c[3])
        : "r"(a0), "r"(a1), "r"(a2), "r"(a3), "r"(b0), "r"(b1));
}

__global__ __launch_bounds__(256)
void mma_gemm_kernel(const float* __restrict__ A, const float* __restrict__ B,
                     float* __restrict__ C, int M, int N, int K,
                     long long strideA, long long strideB, long long strideC,
                     float alpha)
{
    A += (long long)blockIdx.z * strideA;
    B += (long long)blockIdx.z * strideB;
    C += (long long)blockIdx.z * strideC;

    __shared__ __nv_bfloat16 As_hi[128][SM_STRIDE];
    __shared__ __nv_bfloat16 As_lo[128][SM_STRIDE];
    __shared__ __nv_bfloat16 Bs_hi[128][SM_STRIDE];
    __shared__ __nv_bfloat16 Bs_lo[128][SM_STRIDE];

    const int tid   = threadIdx.x;
    const int lane  = tid & 31;
    const int wid   = tid >> 5;
    const int warpM = wid >> 2;          // 0..1
    const int warpN = wid & 3;           // 0..3
    const int g     = lane >> 2;         // groupID 0..7
    const int t2    = (lane & 3) * 2;    // 0,2,4,6

    const int m0 = blockIdx.y * 128;
    const int n0 = blockIdx.x * 128;

    // loader mapping (same for A and B): row = tid>>3 (+32i), col4 = (tid&7)*4
    const int ldR  = tid >> 3;           // 0..31
    const int ldC4 = (tid & 7) * 4;      // 0..28

    float acc[2 /*m-half idx folded*/ * 2][4][4];  // [mi(4)][ni(4)][4] flattened as [4][4][4]
    float (*accv)[4][4] = (float (*)[4][4])acc;
    #pragma unroll
    for (int mi = 0; mi < 4; mi++)
        #pragma unroll
        for (int ni = 0; ni < 4; ni++)
            #pragma unroll
            for (int j = 0; j < 4; j++) accv[mi][ni][j] = 0.0f;

    float4 fa[4], fb[4];

    auto fetch = [&](int k0) {
        #pragma unroll
        for (int i = 0; i < 4; i++) {
            fa[i] = *(const float4*)&A[(size_t)(m0 + ldR + 32 * i) * K + k0 + ldC4];
            fb[i] = *(const float4*)&B[(size_t)(n0 + ldR + 32 * i) * K + k0 + ldC4];
        }
    };
    auto stash = [&]() {
        #pragma unroll
        for (int i = 0; i < 4; i++) {
            const int r = ldR + 32 * i;
            const float* pa = (const float*)&fa[i];
            const float* pb = (const float*)&fb[i];
            #pragma unroll
            for (int j = 0; j < 4; j++) {
                float va = pa[j];
                __nv_bfloat16 ha = __float2bfloat16(va);
                As_hi[r][ldC4 + j] = ha;
                As_lo[r][ldC4 + j] = __float2bfloat16(va - __bfloat162float(ha));
                float vb = pb[j];
                __nv_bfloat16 hb = __float2bfloat16(vb);
                Bs_hi[r][ldC4 + j] = hb;
                Bs_lo[r][ldC4 + j] = __float2bfloat16(vb - __bfloat162float(hb));
            }
        }
    };

    fetch(0);
    stash();
    __syncthreads();

    for (int k0 = 0; k0 < K; k0 += 32) {
        const bool last = (k0 + 32 >= K);
        if (!last) fetch(k0 + 32);

        #pragma unroll
        for (int slab = 0; slab < 2; slab++) {
            const int cb = t2 + slab * 16;

            // B fragments for the 4 n-frags (hi and lo)
            uint32_t bh[4][2], bl[4][2];
            #pragma unroll
            for (int ni = 0; ni < 4; ni++) {
                const int n = warpN * 32 + ni * 8 + g;
                bh[ni][0] = *(const uint32_t*)&Bs_hi[n][cb];
                bh[ni][1] = *(const uint32_t*)&Bs_hi[n][cb + 8];
                bl[ni][0] = *(const uint32_t*)&Bs_lo[n][cb];
                bl[ni][1] = *(const uint32_t*)&Bs_lo[n][cb + 8];
            }

            #pragma unroll
            for (int mi = 0; mi < 4; mi++) {
                const int r0 = warpM * 64 + mi * 16 + g;
                uint32_t ah0 = *(const uint32_t*)&As_hi[r0][cb];
                uint32_t ah1 = *(const uint32_t*)&As_hi[r0 + 8][cb];
                uint32_t ah2 = *(const uint32_t*)&As_hi[r0][cb + 8];
                uint32_t ah3 = *(const uint32_t*)&As_hi[r0 + 8][cb + 8];
                uint32_t al0 = *(const uint32_t*)&As_lo[r0][cb];
                uint32_t al1 = *(const uint32_t*)&As_lo[r0 + 8][cb];
                uint32_t al2 = *(const uint32_t*)&As_lo[r0][cb + 8];
                uint32_t al3 = *(const uint32_t*)&As_lo[r0 + 8][cb + 8];

                #pragma unroll
                for (int ni = 0; ni < 4; ni++) {
                    mma_bf16(accv[mi][ni], ah0, ah1, ah2, ah3, bh[ni][0], bh[ni][1]);
                    mma_bf16(accv[mi][ni], ah0, ah1, ah2, ah3, bl[ni][0], bl[ni][1]);
                    mma_bf16(accv[mi][ni], al0, al1, al2, al3, bh[ni][0], bh[ni][1]);
                }
            }
        }

        if (!last) {
            __syncthreads();
            stash();
            __syncthreads();
        }
    }

    // epilogue: c0,c1 -> (row, col..col+1); c2,c3 -> (row+8, col..col+1)
    #pragma unroll
    for (int mi = 0; mi < 4; mi++) {
        const int row = m0 + warpM * 64 + mi * 16 + g;
        #pragma unroll
        for (int ni = 0; ni < 4; ni++) {
            const int col = n0 + warpN * 32 + ni * 8 + t2;
            float2 v0 = make_float2(alpha * accv[mi][ni][0], alpha * accv[mi][ni][1]);
            float2 v1 = make_float2(alpha * accv[mi][ni][2], alpha * accv[mi][ni][3]);
            *(float2*)&C[(size_t)row * N + col]       = v0;
            *(float2*)&C[(size_t)(row + 8) * N + col] = v1;
        }
    }
}

// ---------------------------------------------------------------------------
// Per-batch transpose: vT[b][d][s] = v[b][s][d].  32x32 smem tiles.
// ---------------------------------------------------------------------------
__global__ __launch_bounds__(256)
void transpose_kernel(const float* __restrict__ v, float* __restrict__ vt)
{
    __shared__ float tile[32][33];
    const int b  = blockIdx.z;
    const int d0 = blockIdx.x * 32;
    const int s0 = blockIdx.y * 32;
    const int tx = threadIdx.x;        // 0..31
    const int ty = threadIdx.y;        // 0..7

    const float* vb  = v  + (size_t)b * S_ * D_;
    float*       vtb = vt + (size_t)b * D_ * S_;

    #pragma unroll
    for (int j = 0; j < 32; j += 8)
        tile[ty + j][tx] = vb[(size_t)(s0 + ty + j) * D_ + d0 + tx];
    __syncthreads();
    #pragma unroll
    for (int j = 0; j < 32; j += 8)
        vtb[(size_t)(d0 + ty + j) * S_ + s0 + tx] = tile[tx][ty + j];
}

// ---------------------------------------------------------------------------
// Register-resident row softmax, one block (256 thr) per row of 2048.
// ---------------------------------------------------------------------------
__global__ __launch_bounds__(256)
void softmax_rows_kernel(float* __restrict__ s)
{
    __shared__ float red[8];
    float* row = s + (size_t)blockIdx.x * S_;
    const int tid  = threadIdx.x;
    const int lane = tid & 31;
    const int wid  = tid >> 5;

    float4 v0 = *(const float4*)&row[tid * 8];
    float4 v1 = *(const float4*)&row[tid * 8 + 4];

    float m = fmaxf(fmaxf(fmaxf(v0.x, v0.y), fmaxf(v0.z, v0.w)),
                    fmaxf(fmaxf(v1.x, v1.y), fmaxf(v1.z, v1.w)));
    #pragma unroll
    for (int off = 16; off > 0; off >>= 1)
        m = fmaxf(m, __shfl_xor_sync(0xffffffffu, m, off));
    if (lane == 0) red[wid] = m;
    __syncthreads();
    m = red[lane & 7];
    #pragma unroll
    for (int off = 4; off > 0; off >>= 1)
        m = fmaxf(m, __shfl_xor_sync(0xffffffffu, m, off));

    v0.x = __expf(v0.x - m); v0.y = __expf(v0.y - m);
    v0.z = __expf(v0.z - m); v0.w = __expf(v0.w - m);
    v1.x = __expf(v1.x - m); v1.y = __expf(v1.y - m);
    v1.z = __expf(v1.z - m); v1.w = __expf(v1.w - m);
    float sum = (v0.x + v0.y) + (v0.z + v0.w) + (v1.x + v1.y) + (v1.z + v1.w);
    #pragma unroll
    for (int off = 16; off > 0; off >>= 1)
        sum += __shfl_xor_sync(0xffffffffu, sum, off);
    __syncthreads();
    if (lane == 0) red[wid] = sum;
    __syncthreads();
    sum = red[lane & 7];
    #pragma unroll
    for (int off = 4; off > 0; off >>= 1)
        sum += __shfl_xor_sync(0xffffffffu, sum, off);

    const float inv = 1.0f / sum;
    v0.x *= inv; v0.y *= inv; v0.z *= inv; v0.w *= inv;
    v1.x *= inv; v1.y *= inv; v1.z *= inv; v1.w *= inv;
    *(float4*)&row[tid * 8]     = v0;
    *(float4*)&row[tid * 8 + 4] = v1;
}

// ---------------------------------------------------------------------------
extern "C" void kernel_launch(void* const* d_in, const int* in_sizes, int n_in,
                              void* d_out, int out_size)
{
    const float* x  = (const float*)d_in[0];
    const float* Wq = (const float*)d_in[1];
    const float* Wk = (const float*)d_in[2];
    const float* Wv = (const float*)d_in[3];
    float* out = (float*)d_out;

    float *q, *k, *v, *vt, *s;
    cudaGetSymbolAddress((void**)&q,  g_q);
    cudaGetSymbolAddress((void**)&k,  g_k);
    cudaGetSymbolAddress((void**)&v,  g_v);
    cudaGetSymbolAddress((void**)&vt, g_vt);
    cudaGetSymbolAddress((void**)&s,  g_s);

    const dim3 blk(256);
    const float scale = 0.088388347648318447f;  // 1/sqrt(128)

    // q = x Wq^T : [16384,1024] x [128,1024] -> [16384,128]
    mma_gemm_kernel<<<dim3(R_ / 128, BS_ / 128, 1), blk>>>(
        x, Wq, q, BS_, R_, D_, 0, 0, 0, 1.0f);
    // k = x Wk^T
    mma_gemm_kernel<<<dim3(R_ / 128, BS_ / 128, 1), blk>>>(
        x, Wk, k, BS_, R_, D_, 0, 0, 0, 1.0f);
    // v = x Wv^T : [16384,1024] x [1024,1024] -> [16384,1024]
    mma_gemm_kernel<<<dim3(D_ / 128, BS_ / 128, 1), blk>>>(
        x, Wv, v, BS_, D_, D_, 0, 0, 0, 1.0f);

    // vT[b][d][s] = v[b][s][d]
    transpose_kernel<<<dim3(D_ / 32, S_ / 32, B_), dim3(32, 8)>>>(v, vt);

    // scores[b] = scale * q[b] k[b]^T : [2048,128] x [2048,128] -> [2048,2048]
    mma_gemm_kernel<<<dim3(S_ / 128, S_ / 128, B_), blk>>>(
        q, k, s, S_, S_, R_,
        (long long)S_ * R_, (long long)S_ * R_, (long long)S_ * S_, scale);

    // softmax rows (register-resident, in place)
    softmax_rows_kernel<<<B_ * S_, blk>>>(s);

    // out[b] = probs[b] @ v[b] = probs [2048,2048(k)] x vT [1024,2048(k)]
    mma_gemm_kernel<<<dim3(D_ / 128, S_ / 128, B_), blk>>>(
        s, vt, out, S_, D_, S_,
        (long long)S_ * S_, (long long)D_ * S_, (long long)S_ * D_, 1.0f);
}

// round 12
// speedup vs baseline: 1.2114x; 1.2114x over previous
#include <cuda_runtime.h>
#include <cuda_bf16.h>
#include <math.h>
#include <stdint.h>

// ---------------------------------------------------------------------------
// PrefilledAttention: x[8,2048,1024] f32; Wq,Wk[128,1024]; Wv[1024,1024]
//   q = x Wq^T; k = x Wk^T; v = x Wv^T
//   s = (q k^T)/sqrt(128); p = softmax(s); out = p v
// Round-12 (= round-8 resubmit, all components audited >=2x): pre-split
// bf16 hi/lo operand planes (convert once in GMEM) + ldmatrix fragment
// loads + mma m16n8k16 3-term split accumulate.
// ---------------------------------------------------------------------------

#define B_   8
#define S_   2048
#define D_   1024
#define R_   128
#define BS_  (B_ * S_)           // 16384

typedef __nv_bfloat16 bf16;

// ---- scratch (no runtime allocation allowed) ----
__device__ bf16  g_xh[(size_t)BS_ * D_], g_xl[(size_t)BS_ * D_];
__device__ bf16  g_wqh[R_ * D_], g_wql[R_ * D_];
__device__ bf16  g_wkh[R_ * D_], g_wkl[R_ * D_];
__device__ bf16  g_wvh[D_ * D_], g_wvl[D_ * D_];
__device__ bf16  g_qh[(size_t)BS_ * R_], g_ql[(size_t)BS_ * R_];
__device__ bf16  g_kh[(size_t)BS_ * R_], g_kl[(size_t)BS_ * R_];
__device__ float g_v [(size_t)BS_ * D_];
__device__ bf16  g_vth[(size_t)BS_ * D_], g_vtl[(size_t)BS_ * D_];    // [B][D][S]
__device__ float g_s [(size_t)B_ * S_ * S_];
__device__ bf16  g_ph[(size_t)B_ * S_ * S_], g_pl[(size_t)B_ * S_ * S_];

// ---------------------------------------------------------------------------
#define SM_STRIDE 40   // bf16 per smem row (80 B row stride, 16B-aligned)

__device__ __forceinline__ void mma_bf16(float c[4],
                                         uint32_t a0, uint32_t a1,
                                         uint32_t a2, uint32_t a3,
                                         uint32_t b0, uint32_t b1)
{
    asm volatile(
        "mma.sync.aligned.m16n8k16.row.col.f32.bf16.bf16.f32 "
        "{%0,%1,%2,%3}, {%4,%5,%6,%7}, {%8,%9}, {%0,%1,%2,%3};\n"
        : "+f"(c[0]), "+f"(c[1]), "+f"(c[2]), "+f"(c[3])
        : "r"(a0), "r"(a1), "r"(a2), "r"(a3), "r"(b0), "r"(b1));
}

__device__ __forceinline__ void ldsm_x4(uint32_t& r0, uint32_t& r1,
                                        uint32_t& r2, uint32_t& r3,
                                        uint32_t addr)
{
    asm volatile("ldmatrix.sync.aligned.m8n8.x4.shared.b16 {%0,%1,%2,%3}, [%4];"
                 : "=r"(r0), "=r"(r1), "=r"(r2), "=r"(r3) : "r"(addr));
}

__device__ __forceinline__ void ldsm_x2(uint32_t& r0, uint32_t& r1, uint32_t addr)
{
    asm volatile("ldmatrix.sync.aligned.m8n8.x2.shared.b16 {%0,%1}, [%2];"
                 : "=r"(r0), "=r"(r1) : "r"(addr));
}

// ---------------------------------------------------------------------------
// Split bf16 tensor-core GEMM:  Cop[m,n] = alpha * sum_k A[m,k] * B[n,k]
// A,B as bf16 hi/lo planes, [M,K]/[N,K] row-major. Block 128x128x32,
// 256 thr (8 warps 2x4), warp tile 64x32, mma m16n8k16, 3-term split.
// SPLIT_OUT: epilogue writes bf16 hi/lo planes instead of f32.
// ---------------------------------------------------------------------------
template <bool SPLIT_OUT>
__global__ __launch_bounds__(256)
void mma_gemm_kernel(const bf16* __restrict__ Ah, const bf16* __restrict__ Al,
                     const bf16* __restrict__ Bh, const bf16* __restrict__ Bl,
                     float* __restrict__ C,
                     bf16* __restrict__ Ch, bf16* __restrict__ Cl,
                     int M, int N, int K,
                     long long strideA, long long strideB, long long strideC,
                     float alpha)
{
    Ah += (long long)blockIdx.z * strideA;  Al += (long long)blockIdx.z * strideA;
    Bh += (long long)blockIdx.z * strideB;  Bl += (long long)blockIdx.z * strideB;
    if (SPLIT_OUT) { Ch += (long long)blockIdx.z * strideC; Cl += (long long)blockIdx.z * strideC; }
    else           { C  += (long long)blockIdx.z * strideC; }

    __shared__ bf16 As_hi[128][SM_STRIDE];
    __shared__ bf16 As_lo[128][SM_STRIDE];
    __shared__ bf16 Bs_hi[128][SM_STRIDE];
    __shared__ bf16 Bs_lo[128][SM_STRIDE];

    const int tid   = threadIdx.x;
    const int lane  = tid & 31;
    const int wid   = tid >> 5;
    const int warpM = wid >> 2;          // 0..1
    const int warpN = wid & 3;           // 0..3
    const int g     = lane >> 2;         // 0..7
    const int t2    = (lane & 3) * 2;    // 0,2,4,6

    const int m0 = blockIdx.y * 128;
    const int n0 = blockIdx.x * 128;

    // global loader: thread t -> row=t>>2 (+64), col8=(t&3)*8
    const int ldR  = tid >> 2;           // 0..63
    const int ldC8 = (tid & 3) * 8;      // 0,8,16,24

    // ldmatrix lane->addr offsets (byte offsets within a plane)
    // A (.x4): matrices (m0k0, m8k0, m0k8, m8k8)
    const int aRow = warpM * 64 + ((lane >> 3) & 1) * 8 + (lane & 7);
    const int aCol = (lane >> 4) * 8;                 // 0 or 8
    const uint32_t offA = (uint32_t)(aRow * SM_STRIDE + aCol) * 2;
    // B (.x2): matrices (n-rows @ k0, n-rows @ k8); lanes 0-7 / 8-15
    const int bRow = lane & 7;
    const int bCol = ((lane >> 3) & 1) * 8;           // 0 or 8
    const uint32_t offB = (uint32_t)((warpN * 32 + bRow) * SM_STRIDE + bCol) * 2;

    const uint32_t baseAh = (uint32_t)__cvta_generic_to_shared(&As_hi[0][0]);
    const uint32_t baseAl = (uint32_t)__cvta_generic_to_shared(&As_lo[0][0]);
    const uint32_t baseBh = (uint32_t)__cvta_generic_to_shared(&Bs_hi[0][0]);
    const uint32_t baseBl = (uint32_t)__cvta_generic_to_shared(&Bs_lo[0][0]);

    float accv[4][4][4];
    #pragma unroll
    for (int mi = 0; mi < 4; mi++)
        #pragma unroll
        for (int ni = 0; ni < 4; ni++)
            #pragma unroll
            for (int j = 0; j < 4; j++) accv[mi][ni][j] = 0.0f;

    uint4 rah[2], ral[2], rbh[2], rbl[2];

    auto fetch = [&](int k0) {
        #pragma unroll
        for (int i = 0; i < 2; i++) {
            const size_t ra = (size_t)(m0 + ldR + 64 * i) * K + k0 + ldC8;
            const size_t rb = (size_t)(n0 + ldR + 64 * i) * K + k0 + ldC8;
            rah[i] = *(const uint4*)&Ah[ra];
            ral[i] = *(const uint4*)&Al[ra];
            rbh[i] = *(const uint4*)&Bh[rb];
            rbl[i] = *(const uint4*)&Bl[rb];
        }
    };
    auto stash = [&]() {
        #pragma unroll
        for (int i = 0; i < 2; i++) {
            const int r = ldR + 64 * i;
            *(uint4*)&As_hi[r][ldC8] = rah[i];
            *(uint4*)&As_lo[r][ldC8] = ral[i];
            *(uint4*)&Bs_hi[r][ldC8] = rbh[i];
            *(uint4*)&Bs_lo[r][ldC8] = rbl[i];
        }
    };

    fetch(0);
    stash();
    __syncthreads();

    for (int k0 = 0; k0 < K; k0 += 32) {
        const bool last = (k0 + 32 >= K);
        if (!last) fetch(k0 + 32);

        #pragma unroll
        for (int slab = 0; slab < 2; slab++) {
            const uint32_t so = slab * 32;   // 16 bf16 = 32 B column shift

            uint32_t bh[4][2], bl[4][2];
            #pragma unroll
            for (int ni = 0; ni < 4; ni++) {
                const uint32_t nio = ni * 8 * SM_STRIDE * 2;
                ldsm_x2(bh[ni][0], bh[ni][1], baseBh + offB + nio + so);
                ldsm_x2(bl[ni][0], bl[ni][1], baseBl + offB + nio + so);
            }

            #pragma unroll
            for (int mi = 0; mi < 4; mi++) {
                const uint32_t mio = mi * 16 * SM_STRIDE * 2;
                uint32_t ah0, ah1, ah2, ah3, al0, al1, al2, al3;
                ldsm_x4(ah0, ah1, ah2, ah3, baseAh + offA + mio + so);
                ldsm_x4(al0, al1, al2, al3, baseAl + offA + mio + so);

                #pragma unroll
                for (int ni = 0; ni < 4; ni++) {
                    mma_bf16(accv[mi][ni], ah0, ah1, ah2, ah3, bh[ni][0], bh[ni][1]);
                    mma_bf16(accv[mi][ni], ah0, ah1, ah2, ah3, bl[ni][0], bl[ni][1]);
                    mma_bf16(accv[mi][ni], al0, al1, al2, al3, bh[ni][0], bh[ni][1]);
                }
            }
        }

        if (!last) {
            __syncthreads();
            stash();
            __syncthreads();
        }
    }

    // epilogue: c0,c1 -> (row, col..col+1); c2,c3 -> (row+8, col..col+1)
    #pragma unroll
    for (int mi = 0; mi < 4; mi++) {
        const int row = m0 + warpM * 64 + mi * 16 + g;
        #pragma unroll
        for (int ni = 0; ni < 4; ni++) {
            const int col = n0 + warpN * 32 + ni * 8 + t2;
            float a0 = alpha * accv[mi][ni][0];
            float a1 = alpha * accv[mi][ni][1];
            float a2 = alpha * accv[mi][ni][2];
            float a3 = alpha * accv[mi][ni][3];
            if (SPLIT_OUT) {
                __nv_bfloat162 h0, l0, h1, l1;
                h0.x = __float2bfloat16(a0);
                h0.y = __float2bfloat16(a1);
                l0.x = __float2bfloat16(a0 - __bfloat162float(h0.x));
                l0.y = __float2bfloat16(a1 - __bfloat162float(h0.y));
                h1.x = __float2bfloat16(a2);
                h1.y = __float2bfloat16(a3);
                l1.x = __float2bfloat16(a2 - __bfloat162float(h1.x));
                l1.y = __float2bfloat16(a3 - __bfloat162float(h1.y));
                *(__nv_bfloat162*)&Ch[(size_t)row * N + col]       = h0;
                *(__nv_bfloat162*)&Cl[(size_t)row * N + col]       = l0;
                *(__nv_bfloat162*)&Ch[(size_t)(row + 8) * N + col] = h1;
                *(__nv_bfloat162*)&Cl[(size_t)(row + 8) * N + col] = l1;
            } else {
                *(float2*)&C[(size_t)row * N + col]       = make_float2(a0, a1);
                *(float2*)&C[(size_t)(row + 8) * N + col] = make_float2(a2, a3);
            }
        }
    }
}

// ---------------------------------------------------------------------------
// Elementwise fp32 -> (hi, lo) bf16 planes. n % 4 == 0.
// ---------------------------------------------------------------------------
__global__ __launch_bounds__(256)
void convert_split_kernel(const float* __restrict__ in,
                          bf16* __restrict__ hi, bf16* __restrict__ lo,
                          long long n)
{
    long long i = ((long long)blockIdx.x * 256 + threadIdx.x) * 4;
    const long long stride = (long long)gridDim.x * 256 * 4;
    for (; i < n; i += stride) {
        float4 v = *(const float4*)&in[i];
        __nv_bfloat162 h0, h1, l0, l1;
        h0.x = __float2bfloat16(v.x); h0.y = __float2bfloat16(v.y);
        h1.x = __float2bfloat16(v.z); h1.y = __float2bfloat16(v.w);
        l0.x = __float2bfloat16(v.x - __bfloat162float(h0.x));
        l0.y = __float2bfloat16(v.y - __bfloat162float(h0.y));
        l1.x = __float2bfloat16(v.z - __bfloat162float(h1.x));
        l1.y = __float2bfloat16(v.w - __bfloat162float(h1.y));
        *(__nv_bfloat162*)&hi[i]     = h0;
        *(__nv_bfloat162*)&hi[i + 2] = h1;
        *(__nv_bfloat162*)&lo[i]     = l0;
        *(__nv_bfloat162*)&lo[i + 2] = l1;
    }
}

// ---------------------------------------------------------------------------
// Per-batch transpose + split: vt{h,l}[b][d][s] = split(v[b][s][d]).
// ---------------------------------------------------------------------------
__global__ __launch_bounds__(256)
void transpose_split_kernel(const float* __restrict__ v,
                            bf16* __restrict__ vth, bf16* __restrict__ vtl)
{
    __shared__ float tile[32][33];
    const int b  = blockIdx.z;
    const int d0 = blockIdx.x * 32;
    const int s0 = blockIdx.y * 32;
    const int tx = threadIdx.x;        // 0..31
    const int ty = threadIdx.y;        // 0..7

    const float* vb = v + (size_t)b * S_ * D_;
    bf16* th = vth + (size_t)b * D_ * S_;
    bf16* tl = vtl + (size_t)b * D_ * S_;

    #pragma unroll
    for (int j = 0; j < 32; j += 8)
        tile[ty + j][tx] = vb[(size_t)(s0 + ty + j) * D_ + d0 + tx];
    __syncthreads();
    #pragma unroll
    for (int j = 0; j < 32; j += 8) {
        float val = tile[tx][ty + j];
        bf16 h = __float2bfloat16(val);
        th[(size_t)(d0 + ty + j) * S_ + s0 + tx] = h;
        tl[(size_t)(d0 + ty + j) * S_ + s0 + tx] =
            __float2bfloat16(val - __bfloat162float(h));
    }
}

// ---------------------------------------------------------------------------
// Register-resident row softmax; emits split bf16 prob planes.
// ---------------------------------------------------------------------------
__global__ __launch_bounds__(256)
void softmax_split_kernel(const float* __restrict__ s,
                          bf16* __restrict__ ph, bf16* __restrict__ pl)
{
    __shared__ float red[8];
    const float* row = s + (size_t)blockIdx.x * S_;
    const int tid  = threadIdx.x;
    const int lane = tid & 31;
    const int wid  = tid >> 5;

    float4 v0 = *(const float4*)&row[tid * 8];
    float4 v1 = *(const float4*)&row[tid * 8 + 4];

    float m = fmaxf(fmaxf(fmaxf(v0.x, v0.y), fmaxf(v0.z, v0.w)),
                    fmaxf(fmaxf(v1.x, v1.y), fmaxf(v1.z, v1.w)));
    #pragma unroll
    for (int off = 16; off > 0; off >>= 1)
        m = fmaxf(m, __shfl_xor_sync(0xffffffffu, m, off));
    if (lane == 0) red[wid] = m;
    __syncthreads();
    m = red[lane & 7];
    #pragma unroll
    for (int off = 4; off > 0; off >>= 1)
        m = fmaxf(m, __shfl_xor_sync(0xffffffffu, m, off));

    v0.x = __expf(v0.x - m); v0.y = __expf(v0.y - m);
    v0.z = __expf(v0.z - m); v0.w = __expf(v0.w - m);
    v1.x = __expf(v1.x - m); v1.y = __expf(v1.y - m);
    v1.z = __expf(v1.z - m); v1.w = __expf(v1.w - m);
    float sum = (v0.x + v0.y) + (v0.z + v0.w) + (v1.x + v1.y) + (v1.z + v1.w);
    #pragma unroll
    for (int off = 16; off > 0; off >>= 1)
        sum += __shfl_xor_sync(0xffffffffu, sum, off);
    __syncthreads();
    if (lane == 0) red[wid] = sum;
    __syncthreads();
    sum = red[lane & 7];
    #pragma unroll
    for (int off = 4; off > 0; off >>= 1)
        sum += __shfl_xor_sync(0xffffffffu, sum, off);

    const float inv = 1.0f / sum;
    float p[8] = { v0.x * inv, v0.y * inv, v0.z * inv, v0.w * inv,
                   v1.x * inv, v1.y * inv, v1.z * inv, v1.w * inv };

    __nv_bfloat162 h[4], l[4];
    #pragma unroll
    for (int j = 0; j < 4; j++) {
        h[j].x = __float2bfloat16(p[2 * j]);
        h[j].y = __float2bfloat16(p[2 * j + 1]);
        l[j].x = __float2bfloat16(p[2 * j]     - __bfloat162float(h[j].x));
        l[j].y = __float2bfloat16(p[2 * j + 1] - __bfloat162float(h[j].y));
    }
    const size_t off8 = (size_t)blockIdx.x * S_ + tid * 8;
    *(uint4*)&ph[off8] = *(uint4*)h;
    *(uint4*)&pl[off8] = *(uint4*)l;
}

// ---------------------------------------------------------------------------
extern "C" void kernel_launch(void* const* d_in, const int* in_sizes, int n_in,
                              void* d_out, int out_size)
{
    const float* x  = (const float*)d_in[0];
    const float* Wq = (const float*)d_in[1];
    const float* Wk = (const float*)d_in[2];
    const float* Wv = (const float*)d_in[3];
    float* out = (float*)d_out;

    bf16 *xh, *xl, *wqh, *wql, *wkh, *wkl, *wvh, *wvl;
    bf16 *qh, *ql, *kh, *kl, *vth, *vtl, *ph, *pl;
    float *v, *s;
    cudaGetSymbolAddress((void**)&xh,  g_xh);  cudaGetSymbolAddress((void**)&xl,  g_xl);
    cudaGetSymbolAddress((void**)&wqh, g_wqh); cudaGetSymbolAddress((void**)&wql, g_wql);
    cudaGetSymbolAddress((void**)&wkh, g_wkh); cudaGetSymbolAddress((void**)&wkl, g_wkl);
    cudaGetSymbolAddress((void**)&wvh, g_wvh); cudaGetSymbolAddress((void**)&wvl, g_wvl);
    cudaGetSymbolAddress((void**)&qh,  g_qh);  cudaGetSymbolAddress((void**)&ql,  g_ql);
    cudaGetSymbolAddress((void**)&kh,  g_kh);  cudaGetSymbolAddress((void**)&kl,  g_kl);
    cudaGetSymbolAddress((void**)&vth, g_vth); cudaGetSymbolAddress((void**)&vtl, g_vtl);
    cudaGetSymbolAddress((void**)&ph,  g_ph);  cudaGetSymbolAddress((void**)&pl,  g_pl);
    cudaGetSymbolAddress((void**)&v,   g_v);
    cudaGetSymbolAddress((void**)&s,   g_s);

    const dim3 blk(256);
    const float scale = 0.088388347648318447f;  // 1/sqrt(128)

    // ---- split inputs once ----
    convert_split_kernel<<<4096, blk>>>(x,  xh,  xl,  (long long)BS_ * D_);
    convert_split_kernel<<<128,  blk>>>(Wq, wqh, wql, (long long)R_ * D_);
    convert_split_kernel<<<128,  blk>>>(Wk, wkh, wkl, (long long)R_ * D_);
    convert_split_kernel<<<1024, blk>>>(Wv, wvh, wvl, (long long)D_ * D_);

    // q = scale * x Wq^T -> split planes   [16384,128]
    mma_gemm_kernel<true><<<dim3(R_ / 128, BS_ / 128, 1), blk>>>(
        xh, xl, wqh, wql, nullptr, qh, ql, BS_, R_, D_, 0, 0, 0, scale);
    // k = x Wk^T -> split planes
    mma_gemm_kernel<true><<<dim3(R_ / 128, BS_ / 128, 1), blk>>>(
        xh, xl, wkh, wkl, nullptr, kh, kl, BS_, R_, D_, 0, 0, 0, 1.0f);
    // v = x Wv^T -> f32                    [16384,1024]
    mma_gemm_kernel<false><<<dim3(D_ / 128, BS_ / 128, 1), blk>>>(
        xh, xl, wvh, wvl, v, nullptr, nullptr, BS_, D_, D_, 0, 0, 0, 1.0f);

    // vt planes: [B][D][S]
    transpose_split_kernel<<<dim3(D_ / 32, S_ / 32, B_), dim3(32, 8)>>>(v, vth, vtl);

    // scores[b] = (scale*q)[b] k[b]^T -> f32  [2048,2048]
    mma_gemm_kernel<false><<<dim3(S_ / 128, S_ / 128, B_), blk>>>(
        qh, ql, kh, kl, s, nullptr, nullptr, S_, S_, R_,
        (long long)S_ * R_, (long long)S_ * R_, (long long)S_ * S_, 1.0f);

    // softmax rows -> split prob planes
    softmax_split_kernel<<<B_ * S_, blk>>>(s, ph, pl);

    // out[b] = p[b] @ v[b] = p [2048,2048(k)] x vt [1024,2048(k)] -> f32
    mma_gemm_kernel<false><<<dim3(D_ / 128, S_ / 128, B_), blk>>>(
        ph, pl, vth, vtl, out, nullptr, nullptr, S_, D_, S_,
        (long long)S_ * S_, (long long)D_ * S_, (long long)S_ * D_, 1.0f);
}

// round 13
// speedup vs baseline: 1.3266x; 1.0951x over previous
#include <cuda_runtime.h>
#include <cuda_bf16.h>
#include <math.h>
#include <stdint.h>

// ---------------------------------------------------------------------------
// PrefilledAttention: x[8,2048,1024] f32; Wq,Wk[128,1024]; Wv[1024,1024]
//   q = x Wq^T; k = x Wk^T; v = x Wv^T
//   s = (q k^T)/sqrt(128); p = softmax(s); out = p v
// Round-13: r12 (pre-split bf16 planes + ldmatrix + 3-term mma) with the
// mainloop rebuilt as a 3-stage cp.async pipeline: one barrier per K-tile,
// 2 tiles of loads always in flight. Everything else byte-identical to r12.
// ---------------------------------------------------------------------------

#define B_   8
#define S_   2048
#define D_   1024
#define R_   128
#define BS_  (B_ * S_)           // 16384

typedef __nv_bfloat16 bf16;

// ---- scratch (no runtime allocation allowed) ----
__device__ bf16  g_xh[(size_t)BS_ * D_], g_xl[(size_t)BS_ * D_];
__device__ bf16  g_wqh[R_ * D_], g_wql[R_ * D_];
__device__ bf16  g_wkh[R_ * D_], g_wkl[R_ * D_];
__device__ bf16  g_wvh[D_ * D_], g_wvl[D_ * D_];
__device__ bf16  g_qh[(size_t)BS_ * R_], g_ql[(size_t)BS_ * R_];
__device__ bf16  g_kh[(size_t)BS_ * R_], g_kl[(size_t)BS_ * R_];
__device__ float g_v [(size_t)BS_ * D_];
__device__ bf16  g_vth[(size_t)BS_ * D_], g_vtl[(size_t)BS_ * D_];    // [B][D][S]
__device__ float g_s [(size_t)B_ * S_ * S_];
__device__ bf16  g_ph[(size_t)B_ * S_ * S_], g_pl[(size_t)B_ * S_ * S_];

// ---------------------------------------------------------------------------
#define SM_STRIDE   40                         // bf16 per smem row (80 B)
#define PLANE_BYTES (128 * SM_STRIDE * 2)      // 10240 B per plane
#define STAGE_BYTES (4 * PLANE_BYTES)          // 40960 B (Ah,Al,Bh,Bl)
#define STAGES      3
#define SMEM_BYTES  (STAGES * STAGE_BYTES)     // 122880 B

__device__ __forceinline__ void mma_bf16(float c[4],
                                         uint32_t a0, uint32_t a1,
                                         uint32_t a2, uint32_t a3,
                                         uint32_t b0, uint32_t b1)
{
    asm volatile(
        "mma.sync.aligned.m16n8k16.row.col.f32.bf16.bf16.f32 "
        "{%0,%1,%2,%3}, {%4,%5,%6,%7}, {%8,%9}, {%0,%1,%2,%3};\n"
        : "+f"(c[0]), "+f"(c[1]), "+f"(c[2]), "+f"(c[3])
        : "r"(a0), "r"(a1), "r"(a2), "r"(a3), "r"(b0), "r"(b1));
}

__device__ __forceinline__ void ldsm_x4(uint32_t& r0, uint32_t& r1,
                                        uint32_t& r2, uint32_t& r3,
                                        uint32_t addr)
{
    asm volatile("ldmatrix.sync.aligned.m8n8.x4.shared.b16 {%0,%1,%2,%3}, [%4];"
                 : "=r"(r0), "=r"(r1), "=r"(r2), "=r"(r3) : "r"(addr));
}

__device__ __forceinline__ void ldsm_x2(uint32_t& r0, uint32_t& r1, uint32_t addr)
{
    asm volatile("ldmatrix.sync.aligned.m8n8.x2.shared.b16 {%0,%1}, [%2];"
                 : "=r"(r0), "=r"(r1) : "r"(addr));
}

__device__ __forceinline__ void cp_async16(uint32_t dst, const void* src)
{
    asm volatile("cp.async.cg.shared.global [%0], [%1], 16;"
                 :: "r"(dst), "l"(src));
}
#define CP_COMMIT() asm volatile("cp.async.commit_group;" ::: "memory")
#define CP_WAIT1()  asm volatile("cp.async.wait_group 1;" ::: "memory")

// ---------------------------------------------------------------------------
// Split bf16 tensor-core GEMM:  Cop[m,n] = alpha * sum_k A[m,k] * B[n,k]
// A,B as bf16 hi/lo planes, [M,K]/[N,K] row-major. Block 128x128x32,
// 256 thr (8 warps 2x4), warp tile 64x32, mma m16n8k16, 3-term split.
// 3-stage cp.async pipeline, one __syncthreads per K-tile.
// SPLIT_OUT: epilogue writes bf16 hi/lo planes instead of f32.
// ---------------------------------------------------------------------------
template <bool SPLIT_OUT>
__global__ __launch_bounds__(256)
void mma_gemm_kernel(const bf16* __restrict__ Ah, const bf16* __restrict__ Al,
                     const bf16* __restrict__ Bh, const bf16* __restrict__ Bl,
                     float* __restrict__ C,
                     bf16* __restrict__ Ch, bf16* __restrict__ Cl,
                     int M, int N, int K,
                     long long strideA, long long strideB, long long strideC,
                     float alpha)
{
    Ah += (long long)blockIdx.z * strideA;  Al += (long long)blockIdx.z * strideA;
    Bh += (long long)blockIdx.z * strideB;  Bl += (long long)blockIdx.z * strideB;
    if (SPLIT_OUT) { Ch += (long long)blockIdx.z * strideC; Cl += (long long)blockIdx.z * strideC; }
    else           { C  += (long long)blockIdx.z * strideC; }

    extern __shared__ char smem_ext[];
    const uint32_t smemBase = (uint32_t)__cvta_generic_to_shared(smem_ext);

    const int tid   = threadIdx.x;
    const int lane  = tid & 31;
    const int wid   = tid >> 5;
    const int warpM = wid >> 2;          // 0..1
    const int warpN = wid & 3;           // 0..3
    const int g     = lane >> 2;         // 0..7
    const int t2    = (lane & 3) * 2;    // 0,2,4,6

    const int m0 = blockIdx.y * 128;
    const int n0 = blockIdx.x * 128;

    // cp.async loader: thread t -> row=t>>2 (+64), col8=(t&3)*8
    const int ldR  = tid >> 2;           // 0..63
    const int ldC8 = (tid & 3) * 8;      // 0,8,16,24

    // ldmatrix lane->addr offsets (byte offsets within a plane)
    // A (.x4): matrices (m0k0, m8k0, m0k8, m8k8)
    const int aRow = warpM * 64 + ((lane >> 3) & 1) * 8 + (lane & 7);
    const int aCol = (lane >> 4) * 8;                 // 0 or 8
    const uint32_t offA = (uint32_t)(aRow * SM_STRIDE + aCol) * 2;
    // B (.x2): lanes 0-7 -> n-rows @ k0, lanes 8-15 -> @ k8
    const int bRow = lane & 7;
    const int bCol = ((lane >> 3) & 1) * 8;           // 0 or 8
    const uint32_t offB = (uint32_t)((warpN * 32 + bRow) * SM_STRIDE + bCol) * 2;

    float accv[4][4][4];
    #pragma unroll
    for (int mi = 0; mi < 4; mi++)
        #pragma unroll
        for (int ni = 0; ni < 4; ni++)
            #pragma unroll
            for (int j = 0; j < 4; j++) accv[mi][ni][j] = 0.0f;

    // issue one K-tile's loads into stage buffer `buf`
    auto issue = [&](int k0, int buf) {
        const uint32_t st = smemBase + buf * STAGE_BYTES;
        #pragma unroll
        for (int i = 0; i < 2; i++) {
            const int r = ldR + 64 * i;
            const uint32_t d = st + (uint32_t)(r * SM_STRIDE + ldC8) * 2;
            const size_t ga = (size_t)(m0 + r) * K + k0 + ldC8;
            const size_t gb = (size_t)(n0 + r) * K + k0 + ldC8;
            cp_async16(d + 0 * PLANE_BYTES, &Ah[ga]);
            cp_async16(d + 1 * PLANE_BYTES, &Al[ga]);
            cp_async16(d + 2 * PLANE_BYTES, &Bh[gb]);
            cp_async16(d + 3 * PLANE_BYTES, &Bl[gb]);
        }
    };

    const int nTiles = K >> 5;   // K/32, K in {128,1024,2048}: >= 4 tiles

    // prologue: fill STAGES-1 = 2 stages
    issue(0, 0);  CP_COMMIT();
    issue(32, 1); CP_COMMIT();
    CP_WAIT1();                  // tile 0 resident
    __syncthreads();

    for (int t = 0; t < nTiles; t++) {
        const int cur = t % STAGES;

        // keep exactly one commit-group per iteration (empty near the tail)
        const int nt = t + STAGES - 1;
        if (nt < nTiles) issue(nt << 5, nt % STAGES);
        CP_COMMIT();

        const uint32_t st = smemBase + cur * STAGE_BYTES;
        #pragma unroll
        for (int slab = 0; slab < 2; slab++) {
            const uint32_t so = slab * 32;   // 16 bf16 = 32 B column shift

            uint32_t bh[4][2], bl[4][2];
            #pragma unroll
            for (int ni = 0; ni < 4; ni++) {
                const uint32_t nio = ni * 8 * SM_STRIDE * 2;
                ldsm_x2(bh[ni][0], bh[ni][1], st + 2 * PLANE_BYTES + offB + nio + so);
                ldsm_x2(bl[ni][0], bl[ni][1], st + 3 * PLANE_BYTES + offB + nio + so);
            }

            #pragma unroll
            for (int mi = 0; mi < 4; mi++) {
                const uint32_t mio = mi * 16 * SM_STRIDE * 2;
                uint32_t ah0, ah1, ah2, ah3, al0, al1, al2, al3;
                ldsm_x4(ah0, ah1, ah2, ah3, st + 0 * PLANE_BYTES + offA + mio + so);
                ldsm_x4(al0, al1, al2, al3, st + 1 * PLANE_BYTES + offA + mio + so);

                #pragma unroll
                for (int ni = 0; ni < 4; ni++) {
                    mma_bf16(accv[mi][ni], ah0, ah1, ah2, ah3, bh[ni][0], bh[ni][1]);
                    mma_bf16(accv[mi][ni], ah0, ah1, ah2, ah3, bl[ni][0], bl[ni][1]);
                    mma_bf16(accv[mi][ni], al0, al1, al2, al3, bh[ni][0], bh[ni][1]);
                }
            }
        }

        CP_WAIT1();              // next tile resident (<=1 group pending)
        __syncthreads();
    }

    // epilogue: c0,c1 -> (row, col..col+1); c2,c3 -> (row+8, col..col+1)
    #pragma unroll
    for (int mi = 0; mi < 4; mi++) {
        const int row = m0 + warpM * 64 + mi * 16 + g;
        #pragma unroll
        for (int ni = 0; ni < 4; ni++) {
            const int col = n0 + warpN * 32 + ni * 8 + t2;
            float a0 = alpha * accv[mi][ni][0];
            float a1 = alpha * accv[mi][ni][1];
            float a2 = alpha * accv[mi][ni][2];
            float a3 = alpha * accv[mi][ni][3];
            if (SPLIT_OUT) {
                __nv_bfloat162 h0, l0, h1, l1;
                h0.x = __float2bfloat16(a0);
                h0.y = __float2bfloat16(a1);
                l0.x = __float2bfloat16(a0 - __bfloat162float(h0.x));
                l0.y = __float2bfloat16(a1 - __bfloat162float(h0.y));
                h1.x = __float2bfloat16(a2);
                h1.y = __float2bfloat16(a3);
                l1.x = __float2bfloat16(a2 - __bfloat162float(h1.x));
                l1.y = __float2bfloat16(a3 - __bfloat162float(h1.y));
                *(__nv_bfloat162*)&Ch[(size_t)row * N + col]       = h0;
                *(__nv_bfloat162*)&Cl[(size_t)row * N + col]       = l0;
                *(__nv_bfloat162*)&Ch[(size_t)(row + 8) * N + col] = h1;
                *(__nv_bfloat162*)&Cl[(size_t)(row + 8) * N + col] = l1;
            } else {
                *(float2*)&C[(size_t)row * N + col]       = make_float2(a0, a1);
                *(float2*)&C[(size_t)(row + 8) * N + col] = make_float2(a2, a3);
            }
        }
    }
}

// ---------------------------------------------------------------------------
// Elementwise fp32 -> (hi, lo) bf16 planes. n % 4 == 0.
// ---------------------------------------------------------------------------
__global__ __launch_bounds__(256)
void convert_split_kernel(const float* __restrict__ in,
                          bf16* __restrict__ hi, bf16* __restrict__ lo,
                          long long n)
{
    long long i = ((long long)blockIdx.x * 256 + threadIdx.x) * 4;
    const long long stride = (long long)gridDim.x * 256 * 4;
    for (; i < n; i += stride) {
        float4 v = *(const float4*)&in[i];
        __nv_bfloat162 h0, h1, l0, l1;
        h0.x = __float2bfloat16(v.x); h0.y = __float2bfloat16(v.y);
        h1.x = __float2bfloat16(v.z); h1.y = __float2bfloat16(v.w);
        l0.x = __float2bfloat16(v.x - __bfloat162float(h0.x));
        l0.y = __float2bfloat16(v.y - __bfloat162float(h0.y));
        l1.x = __float2bfloat16(v.z - __bfloat162float(h1.x));
        l1.y = __float2bfloat16(v.w - __bfloat162float(h1.y));
        *(__nv_bfloat162*)&hi[i]     = h0;
        *(__nv_bfloat162*)&hi[i + 2] = h1;
        *(__nv_bfloat162*)&lo[i]     = l0;
        *(__nv_bfloat162*)&lo[i + 2] = l1;
    }
}

// ---------------------------------------------------------------------------
// Per-batch transpose + split: vt{h,l}[b][d][s] = split(v[b][s][d]).
// ---------------------------------------------------------------------------
__global__ __launch_bounds__(256)
void transpose_split_kernel(const float* __restrict__ v,
                            bf16* __restrict__ vth, bf16* __restrict__ vtl)
{
    __shared__ float tile[32][33];
    const int b  = blockIdx.z;
    const int d0 = blockIdx.x * 32;
    const int s0 = blockIdx.y * 32;
    const int tx = threadIdx.x;        // 0..31
    const int ty = threadIdx.y;        // 0..7

    const float* vb = v + (size_t)b * S_ * D_;
    bf16* th = vth + (size_t)b * D_ * S_;
    bf16* tl = vtl + (size_t)b * D_ * S_;

    #pragma unroll
    for (int j = 0; j < 32; j += 8)
        tile[ty + j][tx] = vb[(size_t)(s0 + ty + j) * D_ + d0 + tx];
    __syncthreads();
    #pragma unroll
    for (int j = 0; j < 32; j += 8) {
        float val = tile[tx][ty + j];
        bf16 h = __float2bfloat16(val);
        th[(size_t)(d0 + ty + j) * S_ + s0 + tx] = h;
        tl[(size_t)(d0 + ty + j) * S_ + s0 + tx] =
            __float2bfloat16(val - __bfloat162float(h));
    }
}

// ---------------------------------------------------------------------------
// Register-resident row softmax; emits split bf16 prob planes.
// ---------------------------------------------------------------------------
__global__ __launch_bounds__(256)
void softmax_split_kernel(const float* __restrict__ s,
                          bf16* __restrict__ ph, bf16* __restrict__ pl)
{
    __shared__ float red[8];
    const float* row = s + (size_t)blockIdx.x * S_;
    const int tid  = threadIdx.x;
    const int lane = tid & 31;
    const int wid  = tid >> 5;

    float4 v0 = *(const float4*)&row[tid * 8];
    float4 v1 = *(const float4*)&row[tid * 8 + 4];

    float m = fmaxf(fmaxf(fmaxf(v0.x, v0.y), fmaxf(v0.z, v0.w)),
                    fmaxf(fmaxf(v1.x, v1.y), fmaxf(v1.z, v1.w)));
    #pragma unroll
    for (int off = 16; off > 0; off >>= 1)
        m = fmaxf(m, __shfl_xor_sync(0xffffffffu, m, off));
    if (lane == 0) red[wid] = m;
    __syncthreads();
    m = red[lane & 7];
    #pragma unroll
    for (int off = 4; off > 0; off >>= 1)
        m = fmaxf(m, __shfl_xor_sync(0xffffffffu, m, off));

    v0.x = __expf(v0.x - m); v0.y = __expf(v0.y - m);
    v0.z = __expf(v0.z - m); v0.w = __expf(v0.w - m);
    v1.x = __expf(v1.x - m); v1.y = __expf(v1.y - m);
    v1.z = __expf(v1.z - m); v1.w = __expf(v1.w - m);
    float sum = (v0.x + v0.y) + (v0.z + v0.w) + (v1.x + v1.y) + (v1.z + v1.w);
    #pragma unroll
    for (int off = 16; off > 0; off >>= 1)
        sum += __shfl_xor_sync(0xffffffffu, sum, off);
    __syncthreads();
    if (lane == 0) red[wid] = sum;
    __syncthreads();
    sum = red[lane & 7];
    #pragma unroll
    for (int off = 4; off > 0; off >>= 1)
        sum += __shfl_xor_sync(0xffffffffu, sum, off);

    const float inv = 1.0f / sum;
    float p[8] = { v0.x * inv, v0.y * inv, v0.z * inv, v0.w * inv,
                   v1.x * inv, v1.y * inv, v1.z * inv, v1.w * inv };

    __nv_bfloat162 h[4], l[4];
    #pragma unroll
    for (int j = 0; j < 4; j++) {
        h[j].x = __float2bfloat16(p[2 * j]);
        h[j].y = __float2bfloat16(p[2 * j + 1]);
        l[j].x = __float2bfloat16(p[2 * j]     - __bfloat162float(h[j].x));
        l[j].y = __float2bfloat16(p[2 * j + 1] - __bfloat162float(h[j].y));
    }
    const size_t off8 = (size_t)blockIdx.x * S_ + tid * 8;
    *(uint4*)&ph[off8] = *(uint4*)h;
    *(uint4*)&pl[off8] = *(uint4*)l;
}

// ---------------------------------------------------------------------------
extern "C" void kernel_launch(void* const* d_in, const int* in_sizes, int n_in,
                              void* d_out, int out_size)
{
    const float* x  = (const float*)d_in[0];
    const float* Wq = (const float*)d_in[1];
    const float* Wk = (const float*)d_in[2];
    const float* Wv = (const float*)d_in[3];
    float* out = (float*)d_out;

    bf16 *xh, *xl, *wqh, *wql, *wkh, *wkl, *wvh, *wvl;
    bf16 *qh, *ql, *kh, *kl, *vth, *vtl, *ph, *pl;
    float *v, *s;
    cudaGetSymbolAddress((void**)&xh,  g_xh);  cudaGetSymbolAddress((void**)&xl,  g_xl);
    cudaGetSymbolAddress((void**)&wqh, g_wqh); cudaGetSymbolAddress((void**)&wql, g_wql);
    cudaGetSymbolAddress((void**)&wkh, g_wkh); cudaGetSymbolAddress((void**)&wkl, g_wkl);
    cudaGetSymbolAddress((void**)&wvh, g_wvh); cudaGetSymbolAddress((void**)&wvl, g_wvl);
    cudaGetSymbolAddress((void**)&qh,  g_qh);  cudaGetSymbolAddress((void**)&ql,  g_ql);
    cudaGetSymbolAddress((void**)&kh,  g_kh);  cudaGetSymbolAddress((void**)&kl,  g_kl);
    cudaGetSymbolAddress((void**)&vth, g_vth); cudaGetSymbolAddress((void**)&vtl, g_vtl);
    cudaGetSymbolAddress((void**)&ph,  g_ph);  cudaGetSymbolAddress((void**)&pl,  g_pl);
    cudaGetSymbolAddress((void**)&v,   g_v);
    cudaGetSymbolAddress((void**)&s,   g_s);

    // opt-in to 120 KB dynamic smem (idempotent, non-stream API)
    cudaFuncSetAttribute(mma_gemm_kernel<true>,
                         cudaFuncAttributeMaxDynamicSharedMemorySize, SMEM_BYTES);
    cudaFuncSetAttribute(mma_gemm_kernel<false>,
                         cudaFuncAttributeMaxDynamicSharedMemorySize, SMEM_BYTES);

    const dim3 blk(256);
    const float scale = 0.088388347648318447f;  // 1/sqrt(128)

    // ---- split inputs once ----
    convert_split_kernel<<<4096, blk>>>(x,  xh,  xl,  (long long)BS_ * D_);
    convert_split_kernel<<<128,  blk>>>(Wq, wqh, wql, (long long)R_ * D_);
    convert_split_kernel<<<128,  blk>>>(Wk, wkh, wkl, (long long)R_ * D_);
    convert_split_kernel<<<1024, blk>>>(Wv, wvh, wvl, (long long)D_ * D_);

    // q = scale * x Wq^T -> split planes   [16384,128]
    mma_gemm_kernel<true><<<dim3(R_ / 128, BS_ / 128, 1), blk, SMEM_BYTES>>>(
        xh, xl, wqh, wql, nullptr, qh, ql, BS_, R_, D_, 0, 0, 0, scale);
    // k = x Wk^T -> split planes
    mma_gemm_kernel<true><<<dim3(R_ / 128, BS_ / 128, 1), blk, SMEM_BYTES>>>(
        xh, xl, wkh, wkl, nullptr, kh, kl, BS_, R_, D_, 0, 0, 0, 1.0f);
    // v = x Wv^T -> f32                    [16384,1024]
    mma_gemm_kernel<false><<<dim3(D_ / 128, BS_ / 128, 1), blk, SMEM_BYTES>>>(
        xh, xl, wvh, wvl, v, nullptr, nullptr, BS_, D_, D_, 0, 0, 0, 1.0f);

    // vt planes: [B][D][S]
    transpose_split_kernel<<<dim3(D_ / 32, S_ / 32, B_), dim3(32, 8)>>>(v, vth, vtl);

    // scores[b] = (scale*q)[b] k[b]^T -> f32  [2048,2048]
    mma_gemm_kernel<false><<<dim3(S_ / 128, S_ / 128, B_), blk, SMEM_BYTES>>>(
        qh, ql, kh, kl, s, nullptr, nullptr, S_, S_, R_,
        (long long)S_ * R_, (long long)S_ * R_, (long long)S_ * S_, 1.0f);

    // softmax rows -> split prob planes
    softmax_split_kernel<<<B_ * S_, blk>>>(s, ph, pl);

    // out[b] = p[b] @ v[b] = p [2048,2048(k)] x vt [1024,2048(k)] -> f32
    mma_gemm_kernel<false><<<dim3(D_ / 128, S_ / 128, B_), blk, SMEM_BYTES>>>(
        ph, pl, vth, vtl, out, nullptr, nullptr, S_, D_, S_,
        (long long)S_ * S_, (long long)D_ * S_, (long long)S_ * D_, 1.0f);
}